// round 2
// baseline (speedup 1.0000x reference)
#include <cuda_runtime.h>
#include <math.h>
#include <stdint.h>

#define NW 6

// Precomputed variational-circuit matrix U (row-major, U[row*64+col]), complex float2 (re, im).
__device__ float2 d_U[64 * 64];

// ---------------- complex helpers ----------------
__device__ __forceinline__ float2 cmul(float2 a, float2 b) {
    return make_float2(a.x * b.x - a.y * b.y, a.x * b.y + a.y * b.x);
}
__device__ __forceinline__ float2 cadd(float2 a, float2 b) {
    return make_float2(a.x + b.x, a.y + b.y);
}
__device__ __forceinline__ float2 cscale(float2 a, float s) {
    return make_float2(a.x * s, a.y * s);
}
__device__ __forceinline__ float2 shflxor(float2 v, int m) {
    v.x = __shfl_xor_sync(0xffffffffu, v.x, m);
    v.y = __shfl_xor_sync(0xffffffffu, v.y, m);
    return v;
}

// ---------------- f32x2 packed helpers ----------------
__device__ __forceinline__ unsigned long long pack2(float a, float b) {
    unsigned long long d;
    asm("mov.b64 %0, {%1,%2};" : "=l"(d) : "f"(a), "f"(b));
    return d;
}
__device__ __forceinline__ void unpack2(unsigned long long v, float& lo, float& hi) {
    asm("mov.b64 {%0,%1}, %2;" : "=f"(lo), "=f"(hi) : "l"(v));
}
__device__ __forceinline__ unsigned long long fma2(unsigned long long a, unsigned long long b,
                                                   unsigned long long c) {
    unsigned long long d;
    asm("fma.rn.f32x2 %0, %1, %2, %3;" : "=l"(d) : "l"(a), "l"(b), "l"(c));
    return d;
}
__device__ __forceinline__ void lds_v2u64(uint32_t addr, unsigned long long& u0,
                                          unsigned long long& u1) {
    asm volatile("ld.shared.v2.b64 {%0,%1}, [%2];" : "=l"(u0), "=l"(u1) : "r"(addr));
}

// ---------------- gate application on warp-held state (build_U) ----------------
// State: 64 complex amplitudes across a warp; lane holds indices n0=2*lane, n1=2*lane+1.
// Wire w corresponds to bit (5-w) of the amplitude index (wire 0 most significant).

__device__ __forceinline__ void apply_diag(float2& s0, float2& s1, int lane, int w,
                                           float2 d0, float2 d1) {
    int bit = 5 - w;
    if (bit == 0) {
        s0 = cmul(s0, d0);
        s1 = cmul(s1, d1);
    } else {
        int mb = (lane >> (bit - 1)) & 1;
        float2 d = mb ? d1 : d0;
        s0 = cmul(s0, d);
        s1 = cmul(s1, d);
    }
}

__device__ __forceinline__ void apply1(float2& s0, float2& s1, int lane, int w,
                                       float2 u00, float2 u01, float2 u10, float2 u11) {
    int bit = 5 - w;
    if (bit == 0) {
        float2 t0 = cadd(cmul(u00, s0), cmul(u01, s1));
        float2 t1 = cadd(cmul(u10, s0), cmul(u11, s1));
        s0 = t0; s1 = t1;
    } else {
        int lm = 1 << (bit - 1);
        float2 p0 = shflxor(s0, lm);
        float2 p1 = shflxor(s1, lm);
        int mb = (lane >> (bit - 1)) & 1;
        if (mb == 0) {
            s0 = cadd(cmul(u00, s0), cmul(u01, p0));
            s1 = cadd(cmul(u00, s1), cmul(u01, p1));
        } else {
            s0 = cadd(cmul(u10, p0), cmul(u11, s0));
            s1 = cadd(cmul(u10, p1), cmul(u11, s1));
        }
    }
}

__device__ __forceinline__ float2 bsu(float2 s, float2 p, int na, int nb,
                                      float c, float sn, float c2, float ex, float ey) {
    if (na == nb) return na ? cscale(s, c2) : s;
    if (na == 0) {
        return make_float2(c * s.x + sn * (ex * p.x - ey * p.y),
                           c * s.y + sn * (ex * p.y + ey * p.x));
    } else {
        return make_float2(c * s.x - sn * (ex * p.x + ey * p.y),
                           c * s.y - sn * (ex * p.y - ey * p.x));
    }
}

__device__ __forceinline__ void apply_bs(float2& s0, float2& s1, int lane, int w,
                                         float th, float ph) {
    float c = cosf(th), sn = sinf(th), c2 = cosf(2.f * th);
    float ex = cosf(ph), ey = sinf(ph);
    int ba = 5 - w, bb = 4 - w;
    float2 p0, p1;
    if (bb >= 1) {
        int lm = ((1 << ba) | (1 << bb)) >> 1;
        p0 = shflxor(s0, lm);
        p1 = shflxor(s1, lm);
    } else {
        p0 = shflxor(s1, 1);
        p1 = shflxor(s0, 1);
    }
    int n0 = lane * 2, n1 = lane * 2 + 1;
    s0 = bsu(s0, p0, (n0 >> ba) & 1, (n0 >> bb) & 1, c, sn, c2, ex, ey);
    s1 = bsu(s1, p1, (n1 >> ba) & 1, (n1 >> bb) & 1, c, sn, c2, ex, ey);
}

// ---------------- Kernel 1: build U columns (64 blocks x 32 threads) ----------------
__global__ void build_U_kernel(const float* __restrict__ var) {
    int col = blockIdx.x;
    int lane = threadIdx.x;
    float2 s0 = make_float2(0.f, 0.f), s1 = make_float2(0.f, 0.f);
    if (lane * 2 == col) s0.x = 1.f;
    if (lane * 2 + 1 == col) s1.x = 1.f;

    for (int l = 0; l < 2; l++) {
        const float* v = var + 50 * l;
        for (int i = 0; i < 5; i++)
            apply_bs(s0, s1, lane, i, __ldg(v + 2 * i), __ldg(v + 2 * i + 1));
        for (int w = 0; w < NW; w++) {
            float ph = __ldg(v + 10 + w);
            float sp, cp; sincosf(ph, &sp, &cp);
            apply_diag(s0, s1, lane, w, make_float2(1.f, 0.f), make_float2(cp, sp));
        }
        for (int w = 0; w < NW; w++) {
            float r = __ldg(v + 16 + w);
            float sech = 1.f / coshf(r);
            float sr = sqrtf(sech);
            apply_diag(s0, s1, lane, w, make_float2(sr, 0.f), make_float2(sech * sr, 0.f));
        }
        for (int i = 0; i < 5; i++)
            apply_bs(s0, s1, lane, i, __ldg(v + 22 + 2 * i), __ldg(v + 23 + 2 * i));
        for (int w = 0; w < NW; w++) {
            float ph = __ldg(v + 32 + w);
            float sp, cp; sincosf(ph, &sp, &cp);
            apply_diag(s0, s1, lane, w, make_float2(1.f, 0.f), make_float2(cp, sp));
        }
        for (int w = 0; w < NW; w++) {
            float r = __ldg(v + 38 + w);
            float pref = expf(-0.5f * r * r);
            apply1(s0, s1, lane, w,
                   make_float2(pref, 0.f), make_float2(-pref * r, 0.f),
                   make_float2(pref * r, 0.f), make_float2(pref * (1.f - r * r), 0.f));
        }
        for (int w = 0; w < NW; w++) {
            float ph = __ldg(v + 44 + w);
            float sp, cp; sincosf(ph, &sp, &cp);
            apply_diag(s0, s1, lane, w, make_float2(1.f, 0.f), make_float2(cp, sp));
        }
    }
    d_U[(lane * 2) * 64 + col] = s0;
    d_U[(lane * 2 + 1) * 64 + col] = s1;
}

// ---------------- Kernel 2: main. 4 threads per sample, 16 rows each. ----------------
__global__ void __launch_bounds__(256, 2)
ffb_main_kernel(const float* __restrict__ x,
                const float* __restrict__ gamma_, const float* __restrict__ beta_,
                float* __restrict__ out, int nsamp) {
    __shared__ __align__(16) float2 sU[64 * 64];   // 32 KB, natural (re, im) layout

    int tid = threadIdx.x;
    {
        const float4* gsrc = (const float4*)d_U;
        float4* sdst = (float4*)sU;
#pragma unroll 4
        for (int i = tid; i < 2048; i += 256) sdst[i] = gsrc[i];
    }
    __syncthreads();

    int gt = blockIdx.x * 256 + tid;
    int s = gt >> 2;           // sample
    int rq = gt & 3;           // row quarter: rows [rq*16, rq*16+16)
    if (s >= nsamp) return;
    const float* xr = x + (size_t)s * 64;

    // ---- encoded product-state amplitudes per wire: alpha (real), beta (complex) ----
    float alw[6];
    float2 bew[6];
#pragma unroll
    for (int w = 0; w < 6; w++) {
        float r1   = __ldg(xr + 2 * w);
        float rd   = __ldg(xr + 28 + 2 * w);
        float phid = __ldg(xr + 29 + 2 * w);
        float phik = __ldg(xr + 40 + w);
        float r2   = __ldg(xr + 46 + 2 * w);
        float phir = __ldg(xr + 58 + w);
        float sech1 = 1.f / coshf(r1);
        float sech2 = 1.f / coshf(r2);
        float pref = __expf(-0.5f * rd * rd);
        float c1 = sqrtf(sech1);
        float ss2 = sqrtf(sech2);
        float base = c1 * pref;
        alw[w] = base * ss2;
        float bm = base * rd * sech2 * ss2;
        float th = phid + phik + phir;
        float sth, cth;
        sincosf(th, &sth, &cth);
        bew[w] = make_float2(bm * cth, bm * sth);
    }

    // half-products: p3 over wires 0..2 (index bits 5..3), q3 over wires 3..5 (bits 2..0)
    float2 p3[8], q3[8];
#pragma unroll
    for (int h = 0; h < 8; h++) {
        float2 t = (h & 4) ? bew[0] : make_float2(alw[0], 0.f);
        t = (h & 2) ? cmul(t, bew[1]) : cscale(t, alw[1]);
        p3[h] = (h & 1) ? cmul(t, bew[2]) : cscale(t, alw[2]);
        float2 u = (h & 4) ? bew[3] : make_float2(alw[3], 0.f);
        u = (h & 2) ? cmul(u, bew[4]) : cscale(u, alw[4]);
        q3[h] = (h & 1) ? cmul(u, bew[5]) : cscale(u, alw[5]);
    }

    // ---- packed complex matvec: rows [rq*16, rq*16+16), all 64 columns ----
    // acc_p[r] += (ar,ar)*(ur,ui) ; acc_m[r] += (ai,ai)*(ur,ui)
    // b_re = acc_p.lo - acc_m.hi ; b_im = acc_p.hi + acc_m.lo
    unsigned long long accp[16], accm[16];
#pragma unroll
    for (int r = 0; r < 16; r++) { accp[r] = 0ull; accm[r] = 0ull; }

    uint32_t su_base = (uint32_t)__cvta_generic_to_shared(sU);
    uint32_t row_addr = su_base + (uint32_t)(rq * 16 * 64) * 8u;  // start of this thread's rows

#pragma unroll
    for (int kc = 0; kc < 8; kc++) {
#pragma unroll
        for (int jp = 0; jp < 4; jp++) {
            float2 a0 = cmul(p3[kc], q3[jp * 2 + 0]);
            float2 a1 = cmul(p3[kc], q3[jp * 2 + 1]);
            unsigned long long a0rr = pack2(a0.x, a0.x);
            unsigned long long a0ii = pack2(a0.y, a0.y);
            unsigned long long a1rr = pack2(a1.x, a1.x);
            unsigned long long a1ii = pack2(a1.y, a1.y);
            uint32_t addr = row_addr + (uint32_t)(kc * 8 + jp * 2) * 8u;
#pragma unroll
            for (int r = 0; r < 16; r++) {
                unsigned long long u0, u1;
                lds_v2u64(addr + (uint32_t)r * 512u, u0, u1);  // cols (j, j+1) of row r
                accp[r] = fma2(a0rr, u0, accp[r]);
                accm[r] = fma2(a0ii, u0, accm[r]);
                accp[r] = fma2(a1rr, u1, accp[r]);
                accm[r] = fma2(a1ii, u1, accm[r]);
            }
        }
    }

    // ---- probs + residual + LayerNorm (4-lane cooperative) ----
    float o[16];
    float sum = 0.f, sumsq = 0.f;
    const float4* xo = (const float4*)xr + rq * 4;
#pragma unroll
    for (int g = 0; g < 4; g++) {
        float4 xv = __ldg(xo + g);
        float xe[4] = {xv.x, xv.y, xv.z, xv.w};
#pragma unroll
        for (int e = 0; e < 4; e++) {
            int r = g * 4 + e;
            float pl, ph, ml, mh;
            unpack2(accp[r], pl, ph);
            unpack2(accm[r], ml, mh);
            float bre = pl - mh;
            float bim = ph + ml;
            float v = fmaf(bre, bre, bim * bim) + xe[e];
            o[r] = v;
            sum += v;
            sumsq = fmaf(v, v, sumsq);
        }
    }
    // reduce across the 4 lanes holding this sample (lanes 4q..4q+3)
    sum += __shfl_xor_sync(0xffffffffu, sum, 1);
    sum += __shfl_xor_sync(0xffffffffu, sum, 2);
    sumsq += __shfl_xor_sync(0xffffffffu, sumsq, 1);
    sumsq += __shfl_xor_sync(0xffffffffu, sumsq, 2);

    float mu = sum * (1.f / 64.f);
    float vv = sumsq * (1.f / 64.f) - mu * mu;
    float rstd = rsqrtf(vv + 1e-5f);

    float4* orow = (float4*)(out + (size_t)s * 64) + rq * 4;
    const float4* gmp = (const float4*)gamma_ + rq * 4;
    const float4* btp = (const float4*)beta_ + rq * 4;
#pragma unroll
    for (int g = 0; g < 4; g++) {
        float4 gm = __ldg(gmp + g);
        float4 bt = __ldg(btp + g);
        float4 ov;
        ov.x = fmaf((o[g * 4 + 0] - mu) * rstd, gm.x, bt.x);
        ov.y = fmaf((o[g * 4 + 1] - mu) * rstd, gm.y, bt.y);
        ov.z = fmaf((o[g * 4 + 2] - mu) * rstd, gm.z, bt.z);
        ov.w = fmaf((o[g * 4 + 3] - mu) * rstd, gm.w, bt.w);
        orow[g] = ov;
    }
}

// ---------------- launch ----------------
extern "C" void kernel_launch(void* const* d_in, const int* in_sizes, int n_in,
                              void* d_out, int out_size) {
    const float* x      = (const float*)d_in[0];
    const float* var    = (const float*)d_in[1];
    const float* gamma_ = (const float*)d_in[2];
    const float* beta_  = (const float*)d_in[3];
    float* out = (float*)d_out;

    int nsamp = in_sizes[0] / 64;

    build_U_kernel<<<64, 32>>>(var);

    int threads = 256;
    int total = nsamp * 4;
    int blocks = (total + threads - 1) / threads;
    ffb_main_kernel<<<blocks, threads>>>(x, gamma_, beta_, out, nsamp);
}

// round 5
// speedup vs baseline: 5.2272x; 5.2272x over previous
#include <cuda_runtime.h>
#include <cuda_bf16.h>
#include <math.h>
#include <stdint.h>

#define NW 6

// W: real 128x128 bf16, row-major. Row n<64 -> br_n weights; row 64+n -> bi_n.
// Col k<64 -> ar_k; col 64+k -> ai_k.
__device__ __align__(16) __nv_bfloat16 d_W[128 * 128];

// ---------------- complex helpers ----------------
__device__ __forceinline__ float2 cmul(float2 a, float2 b) {
    return make_float2(a.x * b.x - a.y * b.y, a.x * b.y + a.y * b.x);
}
__device__ __forceinline__ float2 cadd(float2 a, float2 b) {
    return make_float2(a.x + b.x, a.y + b.y);
}
__device__ __forceinline__ float2 cscale(float2 a, float s) {
    return make_float2(a.x * s, a.y * s);
}
__device__ __forceinline__ float2 shflxor(float2 v, int m) {
    v.x = __shfl_xor_sync(0xffffffffu, v.x, m);
    v.y = __shfl_xor_sync(0xffffffffu, v.y, m);
    return v;
}

// ================= build_W (64 blocks x 32 threads) =================
// Warp-held state: lane holds amplitude indices 2*lane, 2*lane+1; wire w = bit (5-w).

__device__ __forceinline__ void apply_diag(float2& s0, float2& s1, int lane, int w,
                                           float2 d0, float2 d1) {
    int bit = 5 - w;
    if (bit == 0) {
        s0 = cmul(s0, d0);
        s1 = cmul(s1, d1);
    } else {
        int mb = (lane >> (bit - 1)) & 1;
        float2 d = mb ? d1 : d0;
        s0 = cmul(s0, d);
        s1 = cmul(s1, d);
    }
}

__device__ __forceinline__ void apply1(float2& s0, float2& s1, int lane, int w,
                                       float2 u00, float2 u01, float2 u10, float2 u11) {
    int bit = 5 - w;
    if (bit == 0) {
        float2 t0 = cadd(cmul(u00, s0), cmul(u01, s1));
        float2 t1 = cadd(cmul(u10, s0), cmul(u11, s1));
        s0 = t0; s1 = t1;
    } else {
        int lm = 1 << (bit - 1);
        float2 p0 = shflxor(s0, lm);
        float2 p1 = shflxor(s1, lm);
        int mb = (lane >> (bit - 1)) & 1;
        if (mb == 0) {
            s0 = cadd(cmul(u00, s0), cmul(u01, p0));
            s1 = cadd(cmul(u00, s1), cmul(u01, p1));
        } else {
            s0 = cadd(cmul(u10, p0), cmul(u11, s0));
            s1 = cadd(cmul(u10, p1), cmul(u11, s1));
        }
    }
}

__device__ __forceinline__ float2 bsu(float2 s, float2 p, int na, int nb,
                                      float c, float sn, float c2, float ex, float ey) {
    if (na == nb) return na ? cscale(s, c2) : s;
    if (na == 0) {
        return make_float2(c * s.x + sn * (ex * p.x - ey * p.y),
                           c * s.y + sn * (ex * p.y + ey * p.x));
    } else {
        return make_float2(c * s.x - sn * (ex * p.x + ey * p.y),
                           c * s.y - sn * (ex * p.y - ey * p.x));
    }
}

__device__ __forceinline__ void apply_bs(float2& s0, float2& s1, int lane, int w,
                                         float th, float ph) {
    float c = cosf(th), sn = sinf(th), c2 = cosf(2.f * th);
    float ex = cosf(ph), ey = sinf(ph);
    int ba = 5 - w, bb = 4 - w;
    float2 p0, p1;
    if (bb >= 1) {
        int lm = ((1 << ba) | (1 << bb)) >> 1;
        p0 = shflxor(s0, lm);
        p1 = shflxor(s1, lm);
    } else {
        p0 = shflxor(s1, 1);
        p1 = shflxor(s0, 1);
    }
    int n0 = lane * 2, n1 = lane * 2 + 1;
    s0 = bsu(s0, p0, (n0 >> ba) & 1, (n0 >> bb) & 1, c, sn, c2, ex, ey);
    s1 = bsu(s1, p1, (n1 >> ba) & 1, (n1 >> bb) & 1, c, sn, c2, ex, ey);
}

__global__ void build_W_kernel(const float* __restrict__ var) {
    int col = blockIdx.x;   // input basis index k
    int lane = threadIdx.x;
    float2 s0 = make_float2(0.f, 0.f), s1 = make_float2(0.f, 0.f);
    if (lane * 2 == col) s0.x = 1.f;
    if (lane * 2 + 1 == col) s1.x = 1.f;

    for (int l = 0; l < 2; l++) {
        const float* v = var + 50 * l;
        for (int i = 0; i < 5; i++)
            apply_bs(s0, s1, lane, i, __ldg(v + 2 * i), __ldg(v + 2 * i + 1));
        for (int w = 0; w < NW; w++) {
            float ph = __ldg(v + 10 + w);
            float sp, cp; sincosf(ph, &sp, &cp);
            apply_diag(s0, s1, lane, w, make_float2(1.f, 0.f), make_float2(cp, sp));
        }
        for (int w = 0; w < NW; w++) {
            float r = __ldg(v + 16 + w);
            float sech = 1.f / coshf(r);
            float sr = sqrtf(sech);
            apply_diag(s0, s1, lane, w, make_float2(sr, 0.f), make_float2(sech * sr, 0.f));
        }
        for (int i = 0; i < 5; i++)
            apply_bs(s0, s1, lane, i, __ldg(v + 22 + 2 * i), __ldg(v + 23 + 2 * i));
        for (int w = 0; w < NW; w++) {
            float ph = __ldg(v + 32 + w);
            float sp, cp; sincosf(ph, &sp, &cp);
            apply_diag(s0, s1, lane, w, make_float2(1.f, 0.f), make_float2(cp, sp));
        }
        for (int w = 0; w < NW; w++) {
            float r = __ldg(v + 38 + w);
            float pref = expf(-0.5f * r * r);
            apply1(s0, s1, lane, w,
                   make_float2(pref, 0.f), make_float2(-pref * r, 0.f),
                   make_float2(pref * r, 0.f), make_float2(pref * (1.f - r * r), 0.f));
        }
        for (int w = 0; w < NW; w++) {
            float ph = __ldg(v + 44 + w);
            float sp, cp; sincosf(ph, &sp, &cp);
            apply_diag(s0, s1, lane, w, make_float2(1.f, 0.f), make_float2(cp, sp));
        }
    }
    // s0 = U[2*lane, col], s1 = U[2*lane+1, col]
    int k = col;
#pragma unroll
    for (int h = 0; h < 2; h++) {
        float2 u = h ? s1 : s0;
        int r = 2 * lane + h;
        d_W[r * 128 + k]              = __float2bfloat16(u.x);   // br <- ar * Ur
        d_W[r * 128 + 64 + k]         = __float2bfloat16(-u.y);  // br <- ai * (-Ui)
        d_W[(64 + r) * 128 + k]       = __float2bfloat16(u.y);   // bi <- ar * Ui
        d_W[(64 + r) * 128 + 64 + k]  = __float2bfloat16(u.x);   // bi <- ai * Ur
    }
}

// ================= main fused kernel =================
// 128 threads/CTA, 128 samples/CTA, 4 warps x 32 samples.
// smem layout (bytes, from dynamic base):
//   A  : 128 rows x 136 bf16 (stride 68 words)     [0, 34816)
//   Wsm: 128 rows x 136 bf16                        [34816, 69632)
//   Xs : 128 rows x 65 f32                          [69632, 102912)
//   gb : 128 f32 (gamma|beta)                       [102912, 103424)

static constexpr int AS = 136;                       // row stride in bf16 units
static constexpr uint32_t W_OFF  = 128u * AS * 2u;   // 34816
static constexpr uint32_t X_OFF  = W_OFF * 2u;       // 69632
static constexpr uint32_t GB_OFF = X_OFF + 128u * 65u * 4u;  // 102912
static constexpr uint32_t SMEM_DYN = GB_OFF + 512u;  // 103424

__device__ __forceinline__ void mma16816(float c[4], uint32_t a0, uint32_t a1,
                                         uint32_t a2, uint32_t a3,
                                         uint32_t b0, uint32_t b1) {
    asm("mma.sync.aligned.m16n8k16.row.col.f32.bf16.bf16.f32 "
        "{%0,%1,%2,%3}, {%4,%5,%6,%7}, {%8,%9}, {%0,%1,%2,%3};"
        : "+f"(c[0]), "+f"(c[1]), "+f"(c[2]), "+f"(c[3])
        : "r"(a0), "r"(a1), "r"(a2), "r"(a3), "r"(b0), "r"(b1));
}

__global__ void __launch_bounds__(128)
ffb_mma_kernel(const float* __restrict__ x,
               const float* __restrict__ gamma_, const float* __restrict__ beta_,
               float* __restrict__ out, int nsamp) {
    extern __shared__ __align__(16) unsigned char dsm[];
    __nv_bfloat16* As  = (__nv_bfloat16*)(dsm);
    __nv_bfloat16* Ws  = (__nv_bfloat16*)(dsm + W_OFF);
    float* Xs          = (float*)(dsm + X_OFF);
    float* gb          = (float*)(dsm + GB_OFF);

    int tid  = threadIdx.x;
    int wid  = tid >> 5;
    int lane = tid & 31;
    int g    = lane >> 2;
    int t4   = lane & 3;
    int warpM = wid * 32;

    // --- copy W (row tid) into padded smem ---
    {
        const float4* src = (const float4*)(d_W + tid * 128);
        float4* dst = (float4*)(Ws + tid * AS);
#pragma unroll
        for (int i = 0; i < 16; i++) dst[i] = src[i];
    }
    // --- gamma/beta: gb[0..63] = gamma, gb[64..127] = beta ---
    if (tid < 16)      ((float4*)gb)[tid]      = ((const float4*)gamma_)[tid];
    else if (tid < 32) ((float4*)gb)[tid]      = ((const float4*)beta_)[tid - 16];

    // --- prologue: amplitudes for this thread's sample -> A row tid ---
    int s = blockIdx.x * 128 + tid;
    int srd = s < nsamp ? s : (nsamp - 1);
    const float* xr = x + (size_t)srd * 64;

    float alw[6];
    float2 bew[6];
#pragma unroll
    for (int w = 0; w < 6; w++) {
        float r1   = __ldg(xr + 2 * w);
        float rd   = __ldg(xr + 28 + 2 * w);
        float phid = __ldg(xr + 29 + 2 * w);
        float phik = __ldg(xr + 40 + w);
        float r2   = __ldg(xr + 46 + 2 * w);
        float phir = __ldg(xr + 58 + w);
        float e1 = __expf(r1);
        float e2 = __expf(r2);
        float sech1 = 2.f * e1 / (e1 * e1 + 1.f);
        float sech2 = 2.f * e2 / (e2 * e2 + 1.f);
        float pref = __expf(-0.5f * rd * rd);
        float c1 = sqrtf(sech1);
        float ss2 = sqrtf(sech2);
        float base = c1 * pref;
        alw[w] = base * ss2;
        float bm = base * rd * sech2 * ss2;
        float th = phid + phik + phir;
        float sth, cth;
        sincosf(th, &sth, &cth);
        bew[w] = make_float2(bm * cth, bm * sth);
    }
    float2 p3[8], q3[8];
#pragma unroll
    for (int h = 0; h < 8; h++) {
        float2 t = (h & 4) ? bew[0] : make_float2(alw[0], 0.f);
        t = (h & 2) ? cmul(t, bew[1]) : cscale(t, alw[1]);
        p3[h] = (h & 1) ? cmul(t, bew[2]) : cscale(t, alw[2]);
        float2 u = (h & 4) ? bew[3] : make_float2(alw[3], 0.f);
        u = (h & 2) ? cmul(u, bew[4]) : cscale(u, alw[4]);
        q3[h] = (h & 1) ? cmul(u, bew[5]) : cscale(u, alw[5]);
    }
    {
        __nv_bfloat16* arow = As + tid * AS;
#pragma unroll
        for (int i = 0; i < 32; i++) {
            int j0 = (i + (tid & 7) * 4) & 31;  // stagger to reduce STS bank conflicts
            int ja = 2 * j0, jb = 2 * j0 + 1;
            float2 aa = cmul(p3[ja >> 3], q3[ja & 7]);
            float2 ab = cmul(p3[jb >> 3], q3[jb & 7]);
            *(__nv_bfloat162*)(arow + 2 * j0) =
                __nv_bfloat162(__float2bfloat16(aa.x), __float2bfloat16(ab.x));
            *(__nv_bfloat162*)(arow + 64 + 2 * j0) =
                __nv_bfloat162(__float2bfloat16(aa.y), __float2bfloat16(ab.y));
        }
    }

    // --- stage x tile into padded smem (coalesced) ---
    {
        const float4* x4 = (const float4*)x;
        size_t tb4 = (size_t)blockIdx.x * 2048;
        size_t lim = (size_t)nsamp * 16;
#pragma unroll
        for (int i = 0; i < 16; i++) {
            int e = tid + 128 * i;
            size_t gaddr = tb4 + e;
            float4 v = (gaddr < lim) ? __ldg(x4 + gaddr) : make_float4(0.f, 0.f, 0.f, 0.f);
            int row = e >> 4, c = (e & 15) * 4;
            float* p = Xs + row * 65 + c;
            p[0] = v.x; p[1] = v.y; p[2] = v.z; p[3] = v.w;
        }
    }
    __syncthreads();

    // --- GEMM: warp computes C[32 x 128] for samples [warpM, warpM+32) ---
    float c[2][16][4];
#pragma unroll
    for (int t = 0; t < 2; t++)
#pragma unroll
        for (int nt = 0; nt < 16; nt++)
#pragma unroll
            for (int e = 0; e < 4; e++) c[t][nt][e] = 0.f;

#pragma unroll
    for (int ko = 0; ko < 8; ko++) {
        int kc = ko * 16 + t4 * 2;
        uint32_t af[2][4];
#pragma unroll
        for (int t = 0; t < 2; t++) {
            const __nv_bfloat16* r0p = As + (warpM + t * 16 + g) * AS + kc;
            const __nv_bfloat16* r1p = r0p + 8 * AS;
            af[t][0] = *(const uint32_t*)(r0p);
            af[t][1] = *(const uint32_t*)(r1p);
            af[t][2] = *(const uint32_t*)(r0p + 8);
            af[t][3] = *(const uint32_t*)(r1p + 8);
        }
#pragma unroll
        for (int nt = 0; nt < 16; nt++) {
            const __nv_bfloat16* wp = Ws + (nt * 8 + g) * AS + kc;
            uint32_t b0 = *(const uint32_t*)(wp);
            uint32_t b1 = *(const uint32_t*)(wp + 8);
            mma16816(c[0][nt], af[0][0], af[0][1], af[0][2], af[0][3], b0, b1);
            mma16816(c[1][nt], af[1][0], af[1][1], af[1][2], af[1][3], b0, b1);
        }
    }

    // --- epilogue: probs + residual + LayerNorm, in-place in Xs ---
#pragma unroll
    for (int t = 0; t < 2; t++) {
#pragma unroll
        for (int half = 0; half < 2; half++) {
            int row = warpM + t * 16 + g + half * 8;
            float* Xr = Xs + row * 65;
            float v[16];
            float sum = 0.f, sq = 0.f;
#pragma unroll
            for (int nt = 0; nt < 8; nt++) {
                int j = nt * 8 + t4 * 2;
                float br0 = c[t][nt][half * 2 + 0];
                float bi0 = c[t][nt + 8][half * 2 + 0];
                float br1 = c[t][nt][half * 2 + 1];
                float bi1 = c[t][nt + 8][half * 2 + 1];
                float v0 = fmaf(br0, br0, bi0 * bi0) + Xr[j];
                float v1 = fmaf(br1, br1, bi1 * bi1) + Xr[j + 1];
                v[nt * 2] = v0; v[nt * 2 + 1] = v1;
                sum += v0 + v1;
                sq = fmaf(v0, v0, fmaf(v1, v1, sq));
            }
            sum += __shfl_xor_sync(0xffffffffu, sum, 1);
            sum += __shfl_xor_sync(0xffffffffu, sum, 2);
            sq  += __shfl_xor_sync(0xffffffffu, sq, 1);
            sq  += __shfl_xor_sync(0xffffffffu, sq, 2);
            float mu = sum * (1.f / 64.f);
            float vv = sq * (1.f / 64.f) - mu * mu;
            float rstd = rsqrtf(vv + 1e-5f);
#pragma unroll
            for (int nt = 0; nt < 8; nt++) {
                int j = nt * 8 + t4 * 2;
                Xr[j]     = fmaf((v[nt * 2] - mu) * rstd,     gb[j],     gb[64 + j]);
                Xr[j + 1] = fmaf((v[nt * 2 + 1] - mu) * rstd, gb[j + 1], gb[64 + j + 1]);
            }
        }
    }
    __syncthreads();

    // --- coalesced store ---
    {
        float4* o4 = (float4*)out;
        size_t tb4 = (size_t)blockIdx.x * 2048;
        size_t lim = (size_t)nsamp * 16;
#pragma unroll
        for (int i = 0; i < 16; i++) {
            int e = tid + 128 * i;
            int row = e >> 4, cc = (e & 15) * 4;
            float* p = Xs + row * 65 + cc;
            float4 v = make_float4(p[0], p[1], p[2], p[3]);
            size_t gaddr = tb4 + e;
            if (gaddr < lim) o4[gaddr] = v;
        }
    }
}

// ---------------- launch ----------------
extern "C" void kernel_launch(void* const* d_in, const int* in_sizes, int n_in,
                              void* d_out, int out_size) {
    const float* x      = (const float*)d_in[0];
    const float* var    = (const float*)d_in[1];
    const float* gamma_ = (const float*)d_in[2];
    const float* beta_  = (const float*)d_in[3];
    float* out = (float*)d_out;

    int nsamp = in_sizes[0] / 64;

    cudaFuncSetAttribute(ffb_mma_kernel,
                         cudaFuncAttributeMaxDynamicSharedMemorySize, SMEM_DYN);

    build_W_kernel<<<64, 32>>>(var);

    int blocks = (nsamp + 127) / 128;
    ffb_mma_kernel<<<blocks, 128, SMEM_DYN>>>(x, gamma_, beta_, out, nsamp);
}

// round 7
// speedup vs baseline: 6.7929x; 1.2995x over previous
#include <cuda_runtime.h>
#include <cuda_bf16.h>
#include <math.h>
#include <stdint.h>

#define NW 6

// W: real 128x128 bf16, row-major. Row n<64 -> br_n weights; row 64+n -> bi_n.
// Col k<64 -> ar_k; col 64+k -> ai_k.
__device__ __align__(16) __nv_bfloat16 d_W[128 * 128];

// ---------------- complex helpers ----------------
__device__ __forceinline__ float2 cmul(float2 a, float2 b) {
    return make_float2(a.x * b.x - a.y * b.y, a.x * b.y + a.y * b.x);
}
__device__ __forceinline__ float2 cadd(float2 a, float2 b) {
    return make_float2(a.x + b.x, a.y + b.y);
}
__device__ __forceinline__ float2 cscale(float2 a, float s) {
    return make_float2(a.x * s, a.y * s);
}
__device__ __forceinline__ float2 shflxor(float2 v, int m) {
    v.x = __shfl_xor_sync(0xffffffffu, v.x, m);
    v.y = __shfl_xor_sync(0xffffffffu, v.y, m);
    return v;
}

// ================= build_W (64 blocks x 32 threads) =================
__device__ __forceinline__ void apply_diag(float2& s0, float2& s1, int lane, int w,
                                           float2 d0, float2 d1) {
    int bit = 5 - w;
    if (bit == 0) {
        s0 = cmul(s0, d0);
        s1 = cmul(s1, d1);
    } else {
        int mb = (lane >> (bit - 1)) & 1;
        float2 d = mb ? d1 : d0;
        s0 = cmul(s0, d);
        s1 = cmul(s1, d);
    }
}

__device__ __forceinline__ void apply1(float2& s0, float2& s1, int lane, int w,
                                       float2 u00, float2 u01, float2 u10, float2 u11) {
    int bit = 5 - w;
    if (bit == 0) {
        float2 t0 = cadd(cmul(u00, s0), cmul(u01, s1));
        float2 t1 = cadd(cmul(u10, s0), cmul(u11, s1));
        s0 = t0; s1 = t1;
    } else {
        int lm = 1 << (bit - 1);
        float2 p0 = shflxor(s0, lm);
        float2 p1 = shflxor(s1, lm);
        int mb = (lane >> (bit - 1)) & 1;
        if (mb == 0) {
            s0 = cadd(cmul(u00, s0), cmul(u01, p0));
            s1 = cadd(cmul(u00, s1), cmul(u01, p1));
        } else {
            s0 = cadd(cmul(u10, p0), cmul(u11, s0));
            s1 = cadd(cmul(u10, p1), cmul(u11, s1));
        }
    }
}

__device__ __forceinline__ float2 bsu(float2 s, float2 p, int na, int nb,
                                      float c, float sn, float c2, float ex, float ey) {
    if (na == nb) return na ? cscale(s, c2) : s;
    if (na == 0) {
        return make_float2(c * s.x + sn * (ex * p.x - ey * p.y),
                           c * s.y + sn * (ex * p.y + ey * p.x));
    } else {
        return make_float2(c * s.x - sn * (ex * p.x + ey * p.y),
                           c * s.y - sn * (ex * p.y - ey * p.x));
    }
}

__device__ __forceinline__ void apply_bs(float2& s0, float2& s1, int lane, int w,
                                         float th, float ph) {
    float c = cosf(th), sn = sinf(th), c2 = cosf(2.f * th);
    float ex = cosf(ph), ey = sinf(ph);
    int ba = 5 - w, bb = 4 - w;
    float2 p0, p1;
    if (bb >= 1) {
        int lm = ((1 << ba) | (1 << bb)) >> 1;
        p0 = shflxor(s0, lm);
        p1 = shflxor(s1, lm);
    } else {
        p0 = shflxor(s1, 1);
        p1 = shflxor(s0, 1);
    }
    int n0 = lane * 2, n1 = lane * 2 + 1;
    s0 = bsu(s0, p0, (n0 >> ba) & 1, (n0 >> bb) & 1, c, sn, c2, ex, ey);
    s1 = bsu(s1, p1, (n1 >> ba) & 1, (n1 >> bb) & 1, c, sn, c2, ex, ey);
}

__global__ void build_W_kernel(const float* __restrict__ var) {
    int col = blockIdx.x;
    int lane = threadIdx.x;
    float2 s0 = make_float2(0.f, 0.f), s1 = make_float2(0.f, 0.f);
    if (lane * 2 == col) s0.x = 1.f;
    if (lane * 2 + 1 == col) s1.x = 1.f;

    for (int l = 0; l < 2; l++) {
        const float* v = var + 50 * l;
        for (int i = 0; i < 5; i++)
            apply_bs(s0, s1, lane, i, __ldg(v + 2 * i), __ldg(v + 2 * i + 1));
        for (int w = 0; w < NW; w++) {
            float ph = __ldg(v + 10 + w);
            float sp, cp; sincosf(ph, &sp, &cp);
            apply_diag(s0, s1, lane, w, make_float2(1.f, 0.f), make_float2(cp, sp));
        }
        for (int w = 0; w < NW; w++) {
            float r = __ldg(v + 16 + w);
            float sech = 1.f / coshf(r);
            float sr = sqrtf(sech);
            apply_diag(s0, s1, lane, w, make_float2(sr, 0.f), make_float2(sech * sr, 0.f));
        }
        for (int i = 0; i < 5; i++)
            apply_bs(s0, s1, lane, i, __ldg(v + 22 + 2 * i), __ldg(v + 23 + 2 * i));
        for (int w = 0; w < NW; w++) {
            float ph = __ldg(v + 32 + w);
            float sp, cp; sincosf(ph, &sp, &cp);
            apply_diag(s0, s1, lane, w, make_float2(1.f, 0.f), make_float2(cp, sp));
        }
        for (int w = 0; w < NW; w++) {
            float r = __ldg(v + 38 + w);
            float pref = expf(-0.5f * r * r);
            apply1(s0, s1, lane, w,
                   make_float2(pref, 0.f), make_float2(-pref * r, 0.f),
                   make_float2(pref * r, 0.f), make_float2(pref * (1.f - r * r), 0.f));
        }
        for (int w = 0; w < NW; w++) {
            float ph = __ldg(v + 44 + w);
            float sp, cp; sincosf(ph, &sp, &cp);
            apply_diag(s0, s1, lane, w, make_float2(1.f, 0.f), make_float2(cp, sp));
        }
    }
    int k = col;
#pragma unroll
    for (int h = 0; h < 2; h++) {
        float2 u = h ? s1 : s0;
        int r = 2 * lane + h;
        d_W[r * 128 + k]              = __float2bfloat16(u.x);
        d_W[r * 128 + 64 + k]         = __float2bfloat16(-u.y);
        d_W[(64 + r) * 128 + k]       = __float2bfloat16(u.y);
        d_W[(64 + r) * 128 + 64 + k]  = __float2bfloat16(u.x);
    }
}

// ================= main fused kernel =================
// 256 threads/CTA, 128 samples/CTA, 8 warps x 16 samples each.
// smem: A 128 x 136 bf16 [0,34816) ; Ws 128 x 136 bf16 [34816,69632) ; gb 128 f32.

static constexpr int AS = 136;                        // row stride, bf16 units
static constexpr uint32_t W_OFF  = 128u * AS * 2u;    // 34816
static constexpr uint32_t GB_OFF = W_OFF * 2u;        // 69632
static constexpr uint32_t SMEM_DYN = GB_OFF + 512u;   // 70144

__device__ __forceinline__ void mma16816(float c[4], uint32_t a0, uint32_t a1,
                                         uint32_t a2, uint32_t a3,
                                         uint32_t b0, uint32_t b1) {
    asm("mma.sync.aligned.m16n8k16.row.col.f32.bf16.bf16.f32 "
        "{%0,%1,%2,%3}, {%4,%5,%6,%7}, {%8,%9}, {%0,%1,%2,%3};"
        : "+f"(c[0]), "+f"(c[1]), "+f"(c[2]), "+f"(c[3])
        : "r"(a0), "r"(a1), "r"(a2), "r"(a3), "r"(b0), "r"(b1));
}

__device__ __forceinline__ void ldmx4(uint32_t r[4], uint32_t addr) {
    asm volatile("ldmatrix.sync.aligned.m8n8.x4.shared.b16 {%0,%1,%2,%3}, [%4];"
                 : "=r"(r[0]), "=r"(r[1]), "=r"(r[2]), "=r"(r[3]) : "r"(addr));
}

__global__ void __launch_bounds__(256, 2)
ffb_mma_kernel(const float* __restrict__ x,
               const float* __restrict__ gamma_, const float* __restrict__ beta_,
               float* __restrict__ out, int nsamp) {
    extern __shared__ __align__(16) unsigned char dsm[];
    __nv_bfloat16* As = (__nv_bfloat16*)(dsm);
    __nv_bfloat16* Ws = (__nv_bfloat16*)(dsm + W_OFF);
    float* gb         = (float*)(dsm + GB_OFF);

    int tid  = threadIdx.x;
    int wid  = tid >> 5;
    int lane = tid & 31;
    int g    = lane >> 2;
    int t4   = lane & 3;

    if (tid < 128) {
        // ---- prologue: amplitudes for sample (blockBase + tid) -> A row tid ----
        int s = blockIdx.x * 128 + tid;
        int srd = s < nsamp ? s : (nsamp - 1);
        const float* xr = x + (size_t)srd * 64;

        float alw[6];
        float2 bew[6];
#pragma unroll
        for (int w = 0; w < 6; w++) {
            float r1   = __ldg(xr + 2 * w);
            float rd   = __ldg(xr + 28 + 2 * w);
            float phid = __ldg(xr + 29 + 2 * w);
            float phik = __ldg(xr + 40 + w);
            float r2   = __ldg(xr + 46 + 2 * w);
            float phir = __ldg(xr + 58 + w);
            float e1 = __expf(r1);
            float e2 = __expf(r2);
            float sech1 = 2.f * e1 / (e1 * e1 + 1.f);
            float sech2 = 2.f * e2 / (e2 * e2 + 1.f);
            float pref = __expf(-0.5f * rd * rd);
            float c1 = sqrtf(sech1);
            float ss2 = sqrtf(sech2);
            float base = c1 * pref;
            alw[w] = base * ss2;
            float bm = base * rd * sech2 * ss2;
            float th = phid + phik + phir;
            float sth, cth;
            sincosf(th, &sth, &cth);
            bew[w] = make_float2(bm * cth, bm * sth);
        }
        float2 p3[8], q3[8];
#pragma unroll
        for (int h = 0; h < 8; h++) {
            float2 t = (h & 4) ? bew[0] : make_float2(alw[0], 0.f);
            t = (h & 2) ? cmul(t, bew[1]) : cscale(t, alw[1]);
            p3[h] = (h & 1) ? cmul(t, bew[2]) : cscale(t, alw[2]);
            float2 u = (h & 4) ? bew[3] : make_float2(alw[3], 0.f);
            u = (h & 2) ? cmul(u, bew[4]) : cscale(u, alw[4]);
            q3[h] = (h & 1) ? cmul(u, bew[5]) : cscale(u, alw[5]);
        }
        __nv_bfloat16* arow = As + tid * AS;
        int stag = lane >> 3;   // conflict-free stagger (delta 1..3, never 0 mod 4)
#pragma unroll
        for (int i = 0; i < 32; i++) {
            int j0 = (i + stag) & 31;
            int ja = 2 * j0, jb = 2 * j0 + 1;
            float2 aa = cmul(p3[ja >> 3], q3[ja & 7]);
            float2 ab = cmul(p3[jb >> 3], q3[jb & 7]);
            *(__nv_bfloat162*)(arow + 2 * j0) =
                __nv_bfloat162(__float2bfloat16(aa.x), __float2bfloat16(ab.x));
            *(__nv_bfloat162*)(arow + 64 + 2 * j0) =
                __nv_bfloat162(__float2bfloat16(aa.y), __float2bfloat16(ab.y));
        }
    } else {
        // ---- upper half: stage W row (tid-128) and gamma/beta ----
        int r = tid - 128;
        const float4* src = (const float4*)(d_W + r * 128);
        float4* dst = (float4*)(Ws + r * AS);
#pragma unroll
        for (int i = 0; i < 16; i++) dst[i] = src[i];
        if (r < 16)      ((float4*)gb)[r]      = ((const float4*)gamma_)[r];
        else if (r < 32) ((float4*)gb)[r]      = ((const float4*)beta_)[r - 16];
    }
    __syncthreads();

    // ---- GEMM: warp computes C[16 x 128] for samples [wid*16, wid*16+16) ----
    int warpM = wid * 16;
    float c[16][4];
#pragma unroll
    for (int nt = 0; nt < 16; nt++)
#pragma unroll
        for (int e = 0; e < 4; e++) c[nt][e] = 0.f;

    uint32_t asBase = (uint32_t)__cvta_generic_to_shared(As);
    uint32_t wsBase = (uint32_t)__cvta_generic_to_shared(Ws);
    // A ldmatrix lane address: row = warpM + (lane&15), k-half = (lane>>4)*8
    uint32_t aAddr = asBase + (uint32_t)(((warpM + (lane & 15)) * AS + ((lane >> 4) << 3)) * 2);
    // B ldmatrix lane address: n = (lane&7) + ((lane>>4)<<3), k-half = ((lane>>3)&1)*8
    uint32_t bAddr = wsBase + (uint32_t)(((((lane & 7) + ((lane >> 4) << 3)) * AS) +
                                          (((lane >> 3) & 1) << 3)) * 2);

#pragma unroll
    for (int ko = 0; ko < 8; ko++) {
        uint32_t a[4];
        ldmx4(a, aAddr + (uint32_t)(ko * 32));
#pragma unroll
        for (int nt2 = 0; nt2 < 8; nt2++) {
            uint32_t b[4];
            ldmx4(b, bAddr + (uint32_t)(nt2 * 16 * AS * 2 + ko * 32));
            mma16816(c[nt2 * 2],     a[0], a[1], a[2], a[3], b[0], b[1]);
            mma16816(c[nt2 * 2 + 1], a[0], a[1], a[2], a[3], b[2], b[3]);
        }
    }

    // ---- epilogue: probs + residual + LayerNorm, direct global r/w ----
    int blockBase = blockIdx.x * 128;
#pragma unroll
    for (int half = 0; half < 2; half++) {
        int row = blockBase + warpM + g + half * 8;
        int rowc = row < nsamp ? row : (nsamp - 1);
        const float* xrow = x + (size_t)rowc * 64;
        float sum = 0.f, sq = 0.f;
#pragma unroll
        for (int nt = 0; nt < 8; nt++) {
            int j = nt * 8 + t4 * 2;
            float2 xv = __ldg((const float2*)(xrow + j));
            float br0 = c[nt][half * 2 + 0];
            float bi0 = c[nt + 8][half * 2 + 0];
            float br1 = c[nt][half * 2 + 1];
            float bi1 = c[nt + 8][half * 2 + 1];
            float v0 = fmaf(br0, br0, bi0 * bi0) + xv.x;
            float v1 = fmaf(br1, br1, bi1 * bi1) + xv.y;
            c[nt][half * 2 + 0] = v0;       // reuse accumulator storage
            c[nt][half * 2 + 1] = v1;
            sum += v0 + v1;
            sq = fmaf(v0, v0, fmaf(v1, v1, sq));
        }
        sum += __shfl_xor_sync(0xffffffffu, sum, 1);
        sum += __shfl_xor_sync(0xffffffffu, sum, 2);
        sq  += __shfl_xor_sync(0xffffffffu, sq, 1);
        sq  += __shfl_xor_sync(0xffffffffu, sq, 2);
        float mu = sum * (1.f / 64.f);
        float vv = sq * (1.f / 64.f) - mu * mu;
        float rstd = rsqrtf(vv + 1e-5f);
        if (row < nsamp) {
            float* orow = out + (size_t)row * 64;
#pragma unroll
            for (int nt = 0; nt < 8; nt++) {
                int j = nt * 8 + t4 * 2;
                float2 ov;
                ov.x = fmaf((c[nt][half * 2 + 0] - mu) * rstd, gb[j],     gb[64 + j]);
                ov.y = fmaf((c[nt][half * 2 + 1] - mu) * rstd, gb[j + 1], gb[64 + j + 1]);
                *(float2*)(orow + j) = ov;
            }
        }
    }
}

// ---------------- launch ----------------
extern "C" void kernel_launch(void* const* d_in, const int* in_sizes, int n_in,
                              void* d_out, int out_size) {
    const float* x      = (const float*)d_in[0];
    const float* var    = (const float*)d_in[1];
    const float* gamma_ = (const float*)d_in[2];
    const float* beta_  = (const float*)d_in[3];
    float* out = (float*)d_out;

    int nsamp = in_sizes[0] / 64;

    cudaFuncSetAttribute(ffb_mma_kernel,
                         cudaFuncAttributeMaxDynamicSharedMemorySize, SMEM_DYN);

    build_W_kernel<<<64, 32>>>(var);

    int blocks = (nsamp + 127) / 128;
    ffb_mma_kernel<<<blocks, 256, SMEM_DYN>>>(x, gamma_, beta_, out, nsamp);
}

// round 8
// speedup vs baseline: 9.0326x; 1.3297x over previous
#include <cuda_runtime.h>
#include <cuda_bf16.h>
#include <math.h>
#include <stdint.h>

#define NW 6

// W: real 128x128 bf16, row-major. Row n<64 -> br_n weights; row 64+n -> bi_n.
__device__ __align__(16) __nv_bfloat16 d_W[128 * 128];

// ---------------- complex helpers ----------------
__device__ __forceinline__ float2 cmul(float2 a, float2 b) {
    return make_float2(a.x * b.x - a.y * b.y, a.x * b.y + a.y * b.x);
}
__device__ __forceinline__ float2 cadd(float2 a, float2 b) {
    return make_float2(a.x + b.x, a.y + b.y);
}
__device__ __forceinline__ float2 cscale(float2 a, float s) {
    return make_float2(a.x * s, a.y * s);
}
__device__ __forceinline__ float2 shflxor(float2 v, int m) {
    v.x = __shfl_xor_sync(0xffffffffu, v.x, m);
    v.y = __shfl_xor_sync(0xffffffffu, v.y, m);
    return v;
}

// ================= build_W (64 blocks x 32 threads) =================
__device__ __forceinline__ void apply_diag(float2& s0, float2& s1, int lane, int w,
                                           float2 d0, float2 d1) {
    int bit = 5 - w;
    if (bit == 0) {
        s0 = cmul(s0, d0);
        s1 = cmul(s1, d1);
    } else {
        int mb = (lane >> (bit - 1)) & 1;
        float2 d = mb ? d1 : d0;
        s0 = cmul(s0, d);
        s1 = cmul(s1, d);
    }
}

__device__ __forceinline__ void apply1(float2& s0, float2& s1, int lane, int w,
                                       float2 u00, float2 u01, float2 u10, float2 u11) {
    int bit = 5 - w;
    if (bit == 0) {
        float2 t0 = cadd(cmul(u00, s0), cmul(u01, s1));
        float2 t1 = cadd(cmul(u10, s0), cmul(u11, s1));
        s0 = t0; s1 = t1;
    } else {
        int lm = 1 << (bit - 1);
        float2 p0 = shflxor(s0, lm);
        float2 p1 = shflxor(s1, lm);
        int mb = (lane >> (bit - 1)) & 1;
        if (mb == 0) {
            s0 = cadd(cmul(u00, s0), cmul(u01, p0));
            s1 = cadd(cmul(u00, s1), cmul(u01, p1));
        } else {
            s0 = cadd(cmul(u10, p0), cmul(u11, s0));
            s1 = cadd(cmul(u10, p1), cmul(u11, s1));
        }
    }
}

__device__ __forceinline__ float2 bsu(float2 s, float2 p, int na, int nb,
                                      float c, float sn, float c2, float ex, float ey) {
    if (na == nb) return na ? cscale(s, c2) : s;
    if (na == 0) {
        return make_float2(c * s.x + sn * (ex * p.x - ey * p.y),
                           c * s.y + sn * (ex * p.y + ey * p.x));
    } else {
        return make_float2(c * s.x - sn * (ex * p.x + ey * p.y),
                           c * s.y - sn * (ex * p.y - ey * p.x));
    }
}

__device__ __forceinline__ void apply_bs(float2& s0, float2& s1, int lane, int w,
                                         float th, float ph) {
    float c, sn;
    __sincosf(th, &sn, &c);
    float c2 = c * c - sn * sn;
    float ex, ey;
    __sincosf(ph, &ey, &ex);
    int ba = 5 - w, bb = 4 - w;
    float2 p0, p1;
    if (bb >= 1) {
        int lm = ((1 << ba) | (1 << bb)) >> 1;
        p0 = shflxor(s0, lm);
        p1 = shflxor(s1, lm);
    } else {
        p0 = shflxor(s1, 1);
        p1 = shflxor(s0, 1);
    }
    int n0 = lane * 2, n1 = lane * 2 + 1;
    s0 = bsu(s0, p0, (n0 >> ba) & 1, (n0 >> bb) & 1, c, sn, c2, ex, ey);
    s1 = bsu(s1, p1, (n1 >> ba) & 1, (n1 >> bb) & 1, c, sn, c2, ex, ey);
}

__global__ void build_W_kernel(const float* __restrict__ var) {
    int col = blockIdx.x;
    int lane = threadIdx.x;
    float2 s0 = make_float2(0.f, 0.f), s1 = make_float2(0.f, 0.f);
    if (lane * 2 == col) s0.x = 1.f;
    if (lane * 2 + 1 == col) s1.x = 1.f;

    for (int l = 0; l < 2; l++) {
        const float* v = var + 50 * l;
        for (int i = 0; i < 5; i++)
            apply_bs(s0, s1, lane, i, __ldg(v + 2 * i), __ldg(v + 2 * i + 1));
        for (int w = 0; w < NW; w++) {
            float ph = __ldg(v + 10 + w);
            float sp, cp; __sincosf(ph, &sp, &cp);
            apply_diag(s0, s1, lane, w, make_float2(1.f, 0.f), make_float2(cp, sp));
        }
        for (int w = 0; w < NW; w++) {
            float r = __ldg(v + 16 + w);
            float e = __expf(r);
            float sech = 2.f * e / (e * e + 1.f);
            float sr = sqrtf(sech);
            apply_diag(s0, s1, lane, w, make_float2(sr, 0.f), make_float2(sech * sr, 0.f));
        }
        for (int i = 0; i < 5; i++)
            apply_bs(s0, s1, lane, i, __ldg(v + 22 + 2 * i), __ldg(v + 23 + 2 * i));
        for (int w = 0; w < NW; w++) {
            float ph = __ldg(v + 32 + w);
            float sp, cp; __sincosf(ph, &sp, &cp);
            apply_diag(s0, s1, lane, w, make_float2(1.f, 0.f), make_float2(cp, sp));
        }
        for (int w = 0; w < NW; w++) {
            float r = __ldg(v + 38 + w);
            float pref = __expf(-0.5f * r * r);
            apply1(s0, s1, lane, w,
                   make_float2(pref, 0.f), make_float2(-pref * r, 0.f),
                   make_float2(pref * r, 0.f), make_float2(pref * (1.f - r * r), 0.f));
        }
        for (int w = 0; w < NW; w++) {
            float ph = __ldg(v + 44 + w);
            float sp, cp; __sincosf(ph, &sp, &cp);
            apply_diag(s0, s1, lane, w, make_float2(1.f, 0.f), make_float2(cp, sp));
        }
    }
    int k = col;
#pragma unroll
    for (int h = 0; h < 2; h++) {
        float2 u = h ? s1 : s0;
        int r = 2 * lane + h;
        d_W[r * 128 + k]              = __float2bfloat16(u.x);
        d_W[r * 128 + 64 + k]         = __float2bfloat16(-u.y);
        d_W[(64 + r) * 128 + k]       = __float2bfloat16(u.y);
        d_W[(64 + r) * 128 + 64 + k]  = __float2bfloat16(u.x);
    }
}

// ================= main fused kernel =================
// 256 threads/CTA, 128 samples/CTA, 8 warps x 16 samples each.
// smem: A 128x136 bf16 [0,34816) ; Ws 128x136 bf16 [34816,69632) ;
//       Xs 128x65 f32 [69632,102912) ; gb 128 f32 [102912,103424).

static constexpr int AS = 136;                        // row stride, bf16 units
static constexpr uint32_t W_OFF  = 128u * AS * 2u;    // 34816
static constexpr uint32_t X_OFF  = W_OFF * 2u;        // 69632
static constexpr uint32_t GB_OFF = X_OFF + 128u * 65u * 4u;  // 102912
static constexpr uint32_t SMEM_DYN = GB_OFF + 512u;   // 103424

__device__ __forceinline__ void mma16816(float c[4], uint32_t a0, uint32_t a1,
                                         uint32_t a2, uint32_t a3,
                                         uint32_t b0, uint32_t b1) {
    asm("mma.sync.aligned.m16n8k16.row.col.f32.bf16.bf16.f32 "
        "{%0,%1,%2,%3}, {%4,%5,%6,%7}, {%8,%9}, {%0,%1,%2,%3};"
        : "+f"(c[0]), "+f"(c[1]), "+f"(c[2]), "+f"(c[3])
        : "r"(a0), "r"(a1), "r"(a2), "r"(a3), "r"(b0), "r"(b1));
}

__device__ __forceinline__ void ldmx4(uint32_t r[4], uint32_t addr) {
    asm volatile("ldmatrix.sync.aligned.m8n8.x4.shared.b16 {%0,%1,%2,%3}, [%4];"
                 : "=r"(r[0]), "=r"(r[1]), "=r"(r[2]), "=r"(r[3]) : "r"(addr));
}

__global__ void __launch_bounds__(256, 2)
ffb_mma_kernel(const float* __restrict__ x,
               const float* __restrict__ gamma_, const float* __restrict__ beta_,
               float* __restrict__ out, int nsamp) {
    extern __shared__ __align__(16) unsigned char dsm[];
    __nv_bfloat16* As = (__nv_bfloat16*)(dsm);
    __nv_bfloat16* Ws = (__nv_bfloat16*)(dsm + W_OFF);
    float* Xs         = (float*)(dsm + X_OFF);
    float* gb         = (float*)(dsm + GB_OFF);

    int tid  = threadIdx.x;
    int wid  = tid >> 5;
    int lane = tid & 31;
    int g    = lane >> 2;
    int t4   = lane & 3;

    // ---- stage x tile (coalesced float4) into padded Xs ----
    {
        const float4* x4 = (const float4*)x;
        size_t tb4 = (size_t)blockIdx.x * 2048;
        size_t lim = (size_t)nsamp * 16;
#pragma unroll
        for (int i = 0; i < 8; i++) {
            int e = tid + 256 * i;
            size_t gaddr = tb4 + e;
            float4 v = (gaddr < lim) ? __ldg(x4 + gaddr) : make_float4(0.f, 0.f, 0.f, 0.f);
            int row = e >> 4, c = (e & 15) * 4;
            float* p = Xs + row * 65 + c;
            p[0] = v.x; p[1] = v.y; p[2] = v.z; p[3] = v.w;
        }
    }
    // ---- stage W (coalesced) into padded Ws ----
    {
        const float4* src = (const float4*)d_W;
#pragma unroll
        for (int i = 0; i < 8; i++) {
            int e = tid + 256 * i;          // e in [0, 2048)
            int row = e >> 4, c = e & 15;
            *(float4*)(Ws + row * AS + c * 8) = __ldg(src + e);
        }
    }
    if (tid < 16)      ((float4*)gb)[tid] = ((const float4*)gamma_)[tid];
    else if (tid < 32) ((float4*)gb)[tid] = ((const float4*)beta_)[tid - 16];
    __syncthreads();

    // ---- prologue: amplitudes for sample tid (tid<128) from Xs -> A row ----
    if (tid < 128) {
        const float* Xrow = Xs + tid * 65;
        float alw[6];
        float2 bew[6];
#pragma unroll
        for (int w = 0; w < 6; w++) {
            float r1   = Xrow[2 * w];
            float rd   = Xrow[28 + 2 * w];
            float phid = Xrow[29 + 2 * w];
            float phik = Xrow[40 + w];
            float r2   = Xrow[46 + 2 * w];
            float phir = Xrow[58 + w];
            float e1 = __expf(r1);
            float e2 = __expf(r2);
            float sech1 = 2.f * e1 / (e1 * e1 + 1.f);
            float sech2 = 2.f * e2 / (e2 * e2 + 1.f);
            float pref = __expf(-0.5f * rd * rd);
            float c1 = sqrtf(sech1);
            float ss2 = sqrtf(sech2);
            float base = c1 * pref;
            alw[w] = base * ss2;
            float bm = base * rd * sech2 * ss2;
            float th = phid + phik + phir;
            float sth, cth;
            sincosf(th, &sth, &cth);
            bew[w] = make_float2(bm * cth, bm * sth);
        }
        float2 p3[8], q3[8];
#pragma unroll
        for (int h = 0; h < 8; h++) {
            float2 t = (h & 4) ? bew[0] : make_float2(alw[0], 0.f);
            t = (h & 2) ? cmul(t, bew[1]) : cscale(t, alw[1]);
            p3[h] = (h & 1) ? cmul(t, bew[2]) : cscale(t, alw[2]);
            float2 u = (h & 4) ? bew[3] : make_float2(alw[3], 0.f);
            u = (h & 2) ? cmul(u, bew[4]) : cscale(u, alw[4]);
            q3[h] = (h & 1) ? cmul(u, bew[5]) : cscale(u, alw[5]);
        }
        __nv_bfloat16* arow = As + tid * AS;
        int stag = lane >> 3;   // conflict-free stagger
#pragma unroll
        for (int i = 0; i < 32; i++) {
            int j0 = (i + stag) & 31;
            int ja = 2 * j0, jb = 2 * j0 + 1;
            float2 aa = cmul(p3[ja >> 3], q3[ja & 7]);
            float2 ab = cmul(p3[jb >> 3], q3[jb & 7]);
            *(__nv_bfloat162*)(arow + 2 * j0) =
                __nv_bfloat162(__float2bfloat16(aa.x), __float2bfloat16(ab.x));
            *(__nv_bfloat162*)(arow + 64 + 2 * j0) =
                __nv_bfloat162(__float2bfloat16(aa.y), __float2bfloat16(ab.y));
        }
    }
    __syncthreads();

    // ---- GEMM: warp computes C[16 x 128] for samples [wid*16, wid*16+16) ----
    int warpM = wid * 16;
    float c[16][4];
#pragma unroll
    for (int nt = 0; nt < 16; nt++)
#pragma unroll
        for (int e = 0; e < 4; e++) c[nt][e] = 0.f;

    uint32_t asBase = (uint32_t)__cvta_generic_to_shared(As);
    uint32_t wsBase = (uint32_t)__cvta_generic_to_shared(Ws);
    uint32_t aAddr = asBase + (uint32_t)(((warpM + (lane & 15)) * AS + ((lane >> 4) << 3)) * 2);
    uint32_t bAddr = wsBase + (uint32_t)(((((lane & 7) + ((lane >> 4) << 3)) * AS) +
                                          (((lane >> 3) & 1) << 3)) * 2);

#pragma unroll
    for (int ko = 0; ko < 8; ko++) {
        uint32_t a[4];
        ldmx4(a, aAddr + (uint32_t)(ko * 32));
#pragma unroll
        for (int nt2 = 0; nt2 < 8; nt2++) {
            uint32_t b[4];
            ldmx4(b, bAddr + (uint32_t)(nt2 * 16 * AS * 2 + ko * 32));
            mma16816(c[nt2 * 2],     a[0], a[1], a[2], a[3], b[0], b[1]);
            mma16816(c[nt2 * 2 + 1], a[0], a[1], a[2], a[3], b[2], b[3]);
        }
    }

    // ---- epilogue: probs + residual + LayerNorm, write into Xs ----
#pragma unroll
    for (int half = 0; half < 2; half++) {
        int row = warpM + g + half * 8;          // CTA-local sample row
        float* Xr = Xs + row * 65;
        float sum = 0.f, sq = 0.f;
#pragma unroll
        for (int nt = 0; nt < 8; nt++) {
            int j = nt * 8 + t4 * 2;
            float x0 = Xr[j], x1 = Xr[j + 1];
            float br0 = c[nt][half * 2 + 0];
            float bi0 = c[nt + 8][half * 2 + 0];
            float br1 = c[nt][half * 2 + 1];
            float bi1 = c[nt + 8][half * 2 + 1];
            float v0 = fmaf(br0, br0, bi0 * bi0) + x0;
            float v1 = fmaf(br1, br1, bi1 * bi1) + x1;
            c[nt][half * 2 + 0] = v0;
            c[nt][half * 2 + 1] = v1;
            sum += v0 + v1;
            sq = fmaf(v0, v0, fmaf(v1, v1, sq));
        }
        sum += __shfl_xor_sync(0xffffffffu, sum, 1);
        sum += __shfl_xor_sync(0xffffffffu, sum, 2);
        sq  += __shfl_xor_sync(0xffffffffu, sq, 1);
        sq  += __shfl_xor_sync(0xffffffffu, sq, 2);
        float mu = sum * (1.f / 64.f);
        float vv = sq * (1.f / 64.f) - mu * mu;
        float rstd = rsqrtf(vv + 1e-5f);
#pragma unroll
        for (int nt = 0; nt < 8; nt++) {
            int j = nt * 8 + t4 * 2;
            Xr[j]     = fmaf((c[nt][half * 2 + 0] - mu) * rstd, gb[j],     gb[64 + j]);
            Xr[j + 1] = fmaf((c[nt][half * 2 + 1] - mu) * rstd, gb[j + 1], gb[64 + j + 1]);
        }
    }
    __syncthreads();

    // ---- coalesced store out ----
    {
        float4* o4 = (float4*)out;
        size_t tb4 = (size_t)blockIdx.x * 2048;
        size_t lim = (size_t)nsamp * 16;
#pragma unroll
        for (int i = 0; i < 8; i++) {
            int e = tid + 256 * i;
            int row = e >> 4, cc = (e & 15) * 4;
            float* p = Xs + row * 65 + cc;
            float4 v = make_float4(p[0], p[1], p[2], p[3]);
            size_t gaddr = tb4 + e;
            if (gaddr < lim) o4[gaddr] = v;
        }
    }
}

// ---------------- launch ----------------
extern "C" void kernel_launch(void* const* d_in, const int* in_sizes, int n_in,
                              void* d_out, int out_size) {
    const float* x      = (const float*)d_in[0];
    const float* var    = (const float*)d_in[1];
    const float* gamma_ = (const float*)d_in[2];
    const float* beta_  = (const float*)d_in[3];
    float* out = (float*)d_out;

    int nsamp = in_sizes[0] / 64;

    cudaFuncSetAttribute(ffb_mma_kernel,
                         cudaFuncAttributeMaxDynamicSharedMemorySize, SMEM_DYN);

    build_W_kernel<<<64, 32>>>(var);

    int blocks = (nsamp + 127) / 128;
    ffb_mma_kernel<<<blocks, 256, SMEM_DYN>>>(x, gamma_, beta_, out, nsamp);
}

// round 10
// speedup vs baseline: 10.1849x; 1.1276x over previous
#include <cuda_runtime.h>
#include <cuda_bf16.h>
#include <math.h>
#include <stdint.h>

#define NW 6

// W: real 128x128 bf16, row-major. Row n<64 -> br_n weights; row 64+n -> bi_n.
__device__ __align__(16) __nv_bfloat16 d_W[128 * 128];

// ---------------- complex helpers ----------------
__device__ __forceinline__ float2 cmul(float2 a, float2 b) {
    return make_float2(a.x * b.x - a.y * b.y, a.x * b.y + a.y * b.x);
}
__device__ __forceinline__ float2 cadd(float2 a, float2 b) {
    return make_float2(a.x + b.x, a.y + b.y);
}
__device__ __forceinline__ float2 cscale(float2 a, float s) {
    return make_float2(a.x * s, a.y * s);
}
__device__ __forceinline__ float2 shflxor(float2 v, int m) {
    v.x = __shfl_xor_sync(0xffffffffu, v.x, m);
    v.y = __shfl_xor_sync(0xffffffffu, v.y, m);
    return v;
}

// ================= build_W (64 blocks x 32 threads) =================
__device__ __forceinline__ void apply_diag(float2& s0, float2& s1, int lane, int w,
                                           float2 d0, float2 d1) {
    int bit = 5 - w;
    if (bit == 0) {
        s0 = cmul(s0, d0);
        s1 = cmul(s1, d1);
    } else {
        int mb = (lane >> (bit - 1)) & 1;
        float2 d = mb ? d1 : d0;
        s0 = cmul(s0, d);
        s1 = cmul(s1, d);
    }
}

__device__ __forceinline__ void apply1(float2& s0, float2& s1, int lane, int w,
                                       float2 u00, float2 u01, float2 u10, float2 u11) {
    int bit = 5 - w;
    if (bit == 0) {
        float2 t0 = cadd(cmul(u00, s0), cmul(u01, s1));
        float2 t1 = cadd(cmul(u10, s0), cmul(u11, s1));
        s0 = t0; s1 = t1;
    } else {
        int lm = 1 << (bit - 1);
        float2 p0 = shflxor(s0, lm);
        float2 p1 = shflxor(s1, lm);
        int mb = (lane >> (bit - 1)) & 1;
        if (mb == 0) {
            s0 = cadd(cmul(u00, s0), cmul(u01, p0));
            s1 = cadd(cmul(u00, s1), cmul(u01, p1));
        } else {
            s0 = cadd(cmul(u10, p0), cmul(u11, s0));
            s1 = cadd(cmul(u10, p1), cmul(u11, s1));
        }
    }
}

__device__ __forceinline__ float2 bsu(float2 s, float2 p, int na, int nb,
                                      float c, float sn, float c2, float ex, float ey) {
    if (na == nb) return na ? cscale(s, c2) : s;
    if (na == 0) {
        return make_float2(c * s.x + sn * (ex * p.x - ey * p.y),
                           c * s.y + sn * (ex * p.y + ey * p.x));
    } else {
        return make_float2(c * s.x - sn * (ex * p.x + ey * p.y),
                           c * s.y - sn * (ex * p.y - ey * p.x));
    }
}

__device__ __forceinline__ void apply_bs(float2& s0, float2& s1, int lane, int w,
                                         float th, float ph) {
    float c, sn;
    __sincosf(th, &sn, &c);
    float c2 = c * c - sn * sn;
    float ex, ey;
    __sincosf(ph, &ey, &ex);
    int ba = 5 - w, bb = 4 - w;
    float2 p0, p1;
    if (bb >= 1) {
        int lm = ((1 << ba) | (1 << bb)) >> 1;
        p0 = shflxor(s0, lm);
        p1 = shflxor(s1, lm);
    } else {
        p0 = shflxor(s1, 1);
        p1 = shflxor(s0, 1);
    }
    int n0 = lane * 2, n1 = lane * 2 + 1;
    s0 = bsu(s0, p0, (n0 >> ba) & 1, (n0 >> bb) & 1, c, sn, c2, ex, ey);
    s1 = bsu(s1, p1, (n1 >> ba) & 1, (n1 >> bb) & 1, c, sn, c2, ex, ey);
}

__global__ void build_W_kernel(const float* __restrict__ var) {
    int col = blockIdx.x;
    int lane = threadIdx.x;
    float2 s0 = make_float2(0.f, 0.f), s1 = make_float2(0.f, 0.f);
    if (lane * 2 == col) s0.x = 1.f;
    if (lane * 2 + 1 == col) s1.x = 1.f;

    for (int l = 0; l < 2; l++) {
        const float* v = var + 50 * l;
        for (int i = 0; i < 5; i++)
            apply_bs(s0, s1, lane, i, __ldg(v + 2 * i), __ldg(v + 2 * i + 1));
        for (int w = 0; w < NW; w++) {
            float ph = __ldg(v + 10 + w);
            float sp, cp; __sincosf(ph, &sp, &cp);
            apply_diag(s0, s1, lane, w, make_float2(1.f, 0.f), make_float2(cp, sp));
        }
        for (int w = 0; w < NW; w++) {
            float r = __ldg(v + 16 + w);
            float e = __expf(r);
            float sech = __fdividef(2.f * e, fmaf(e, e, 1.f));
            float sr = sqrtf(sech);
            apply_diag(s0, s1, lane, w, make_float2(sr, 0.f), make_float2(sech * sr, 0.f));
        }
        for (int i = 0; i < 5; i++)
            apply_bs(s0, s1, lane, i, __ldg(v + 22 + 2 * i), __ldg(v + 23 + 2 * i));
        for (int w = 0; w < NW; w++) {
            float ph = __ldg(v + 32 + w);
            float sp, cp; __sincosf(ph, &sp, &cp);
            apply_diag(s0, s1, lane, w, make_float2(1.f, 0.f), make_float2(cp, sp));
        }
        for (int w = 0; w < NW; w++) {
            float r = __ldg(v + 38 + w);
            float pref = __expf(-0.5f * r * r);
            apply1(s0, s1, lane, w,
                   make_float2(pref, 0.f), make_float2(-pref * r, 0.f),
                   make_float2(pref * r, 0.f), make_float2(pref * (1.f - r * r), 0.f));
        }
        for (int w = 0; w < NW; w++) {
            float ph = __ldg(v + 44 + w);
            float sp, cp; __sincosf(ph, &sp, &cp);
            apply_diag(s0, s1, lane, w, make_float2(1.f, 0.f), make_float2(cp, sp));
        }
    }
    int k = col;
#pragma unroll
    for (int h = 0; h < 2; h++) {
        float2 u = h ? s1 : s0;
        int r = 2 * lane + h;
        d_W[r * 128 + k]              = __float2bfloat16(u.x);
        d_W[r * 128 + 64 + k]         = __float2bfloat16(-u.y);
        d_W[(64 + r) * 128 + k]       = __float2bfloat16(u.y);
        d_W[(64 + r) * 128 + 64 + k]  = __float2bfloat16(u.x);
    }
}

// ================= main fused kernel =================
// 256 threads/CTA, 128 samples/CTA, 8 warps x 16 samples each.
// smem: A 128x136 bf16 [0,34816) ; Ws 128x136 bf16 [34816,69632) ;
//       Xs 128x65 f32 [69632,102912) ; gb 128 f32 [102912,103424).

static constexpr int AS = 136;                        // row stride, bf16 units
static constexpr uint32_t W_OFF  = 128u * AS * 2u;    // 34816
static constexpr uint32_t X_OFF  = W_OFF * 2u;        // 69632
static constexpr uint32_t GB_OFF = X_OFF + 128u * 65u * 4u;  // 102912
static constexpr uint32_t SMEM_DYN = GB_OFF + 512u;   // 103424

__device__ __forceinline__ void mma16816(float c[4], uint32_t a0, uint32_t a1,
                                         uint32_t a2, uint32_t a3,
                                         uint32_t b0, uint32_t b1) {
    asm("mma.sync.aligned.m16n8k16.row.col.f32.bf16.bf16.f32 "
        "{%0,%1,%2,%3}, {%4,%5,%6,%7}, {%8,%9}, {%0,%1,%2,%3};"
        : "+f"(c[0]), "+f"(c[1]), "+f"(c[2]), "+f"(c[3])
        : "r"(a0), "r"(a1), "r"(a2), "r"(a3), "r"(b0), "r"(b1));
}

__device__ __forceinline__ void ldmx4(uint32_t r[4], uint32_t addr) {
    asm volatile("ldmatrix.sync.aligned.m8n8.x4.shared.b16 {%0,%1,%2,%3}, [%4];"
                 : "=r"(r[0]), "=r"(r[1]), "=r"(r[2]), "=r"(r[3]) : "r"(addr));
}

__global__ void __launch_bounds__(256, 2)
ffb_mma_kernel(const float* __restrict__ x,
               const float* __restrict__ gamma_, const float* __restrict__ beta_,
               float* __restrict__ out, int nsamp) {
    extern __shared__ __align__(16) unsigned char dsm[];
    __nv_bfloat16* As = (__nv_bfloat16*)(dsm);
    __nv_bfloat16* Ws = (__nv_bfloat16*)(dsm + W_OFF);
    float* Xs         = (float*)(dsm + X_OFF);
    float* gb         = (float*)(dsm + GB_OFF);

    int tid  = threadIdx.x;
    int wid  = tid >> 5;
    int lane = tid & 31;
    int g    = lane >> 2;
    int t4   = lane & 3;

    // ---- stage x tile (coalesced float4) into padded Xs ----
    {
        const float4* x4 = (const float4*)x;
        size_t tb4 = (size_t)blockIdx.x * 2048;
        size_t lim = (size_t)nsamp * 16;
#pragma unroll
        for (int i = 0; i < 8; i++) {
            int e = tid + 256 * i;
            size_t gaddr = tb4 + e;
            float4 v = (gaddr < lim) ? __ldg(x4 + gaddr) : make_float4(0.f, 0.f, 0.f, 0.f);
            int row = e >> 4, c = (e & 15) * 4;
            float* p = Xs + row * 65 + c;
            p[0] = v.x; p[1] = v.y; p[2] = v.z; p[3] = v.w;
        }
    }
    // ---- stage W (coalesced) into padded Ws ----
    {
        const float4* src = (const float4*)d_W;
#pragma unroll
        for (int i = 0; i < 8; i++) {
            int e = tid + 256 * i;
            int row = e >> 4, c = e & 15;
            *(float4*)(Ws + row * AS + c * 8) = __ldg(src + e);
        }
    }
    if (tid < 16)      ((float4*)gb)[tid] = ((const float4*)gamma_)[tid];
    else if (tid < 32) ((float4*)gb)[tid] = ((const float4*)beta_)[tid - 16];
    __syncthreads();

    // ---- prologue (tid<128): MUFU-lean amplitude computation ----
    if (tid < 128) {
        const float* Xrow = Xs + tid * 65;
        float2 P3[8], Q3[8];

#pragma unroll
        for (int hf = 0; hf < 2; hf++) {
            int wb = 3 * hf;
            float e2v[3], qv[3], rdv[3];
            float2 cs[3];
            float Pp = 1.f, Ep = 1.f, rdsq = 0.f;
#pragma unroll
            for (int i = 0; i < 3; i++) {
                int w = wb + i;
                float r1   = Xrow[2 * w];
                float rd   = Xrow[28 + 2 * w];
                float phid = Xrow[29 + 2 * w];
                float phik = Xrow[40 + w];
                float r2   = Xrow[46 + 2 * w];
                float phir = Xrow[58 + w];
                float e1 = __expf(r1);
                float e2 = __expf(r2);
                e2v[i] = e2;
                qv[i] = fmaf(e2, e2, 1.f);
                Pp *= fmaf(e1, e1, 1.f);
                Ep *= e1 * e2;
                rdv[i] = rd;
                rdsq = fmaf(rd, rd, rdsq);
                float th = phid + phik + phir;
                float sth, cth;
                __sincosf(th, &sth, &cth);
                cs[i] = make_float2(cth, sth);
            }
            float prefH = __expf(-0.5f * rdsq);
            float Qp = qv[0] * qv[1] * qv[2];
            float rQ  = __fdividef(1.f, Qp);
            float rPQ = __fdividef(1.f, Pp * Qp);
            float sH = 64.f * Ep * rPQ;                  // prod sech1*sech2
            float AH = prefH * sqrtf(sH);
            // T_w = rd_w * sech2_w * e^{i th_w};  sech2_w = 2 e2 q_o1 q_o2 * rQ
            float2 T0 = cscale(cs[0], rdv[0] * 2.f * e2v[0] * qv[1] * qv[2] * rQ);
            float2 T1 = cscale(cs[1], rdv[1] * 2.f * e2v[1] * qv[0] * qv[2] * rQ);
            float2 T2 = cscale(cs[2], rdv[2] * 2.f * e2v[2] * qv[0] * qv[1] * rQ);

            float2* H = hf ? Q3 : P3;
            H[0] = make_float2(AH, 0.f);
            H[1] = cscale(T2, AH);
            H[2] = cscale(T1, AH);
            H[3] = cmul(H[2], T2);
            H[4] = cscale(T0, AH);
            H[5] = cmul(H[4], T2);
            H[6] = cmul(H[4], T1);
            H[7] = cmul(H[6], T2);
        }

        __nv_bfloat16* arow = As + tid * AS;
        int stag = lane >> 3;   // conflict-free stagger
#pragma unroll
        for (int i = 0; i < 32; i++) {
            int j0 = (i + stag) & 31;
            int ja = 2 * j0, jb = 2 * j0 + 1;
            float2 aa = cmul(P3[ja >> 3], Q3[ja & 7]);
            float2 ab = cmul(P3[jb >> 3], Q3[jb & 7]);
            *(__nv_bfloat162*)(arow + 2 * j0) =
                __nv_bfloat162(__float2bfloat16(aa.x), __float2bfloat16(ab.x));
            *(__nv_bfloat162*)(arow + 64 + 2 * j0) =
                __nv_bfloat162(__float2bfloat16(aa.y), __float2bfloat16(ab.y));
        }
    }
    __syncthreads();

    // ---- GEMM: warp computes C[16 x 128] for samples [wid*16, wid*16+16) ----
    int warpM = wid * 16;
    float c[16][4];
#pragma unroll
    for (int nt = 0; nt < 16; nt++)
#pragma unroll
        for (int e = 0; e < 4; e++) c[nt][e] = 0.f;

    uint32_t asBase = (uint32_t)__cvta_generic_to_shared(As);
    uint32_t wsBase = (uint32_t)__cvta_generic_to_shared(Ws);
    uint32_t aAddr = asBase + (uint32_t)(((warpM + (lane & 15)) * AS + ((lane >> 4) << 3)) * 2);
    uint32_t bAddr = wsBase + (uint32_t)(((((lane & 7) + ((lane >> 4) << 3)) * AS) +
                                          (((lane >> 3) & 1) << 3)) * 2);

#pragma unroll
    for (int ko = 0; ko < 8; ko++) {
        uint32_t a[4];
        ldmx4(a, aAddr + (uint32_t)(ko * 32));
#pragma unroll
        for (int nt2 = 0; nt2 < 8; nt2++) {
            uint32_t b[4];
            ldmx4(b, bAddr + (uint32_t)(nt2 * 16 * AS * 2 + ko * 32));
            mma16816(c[nt2 * 2],     a[0], a[1], a[2], a[3], b[0], b[1]);
            mma16816(c[nt2 * 2 + 1], a[0], a[1], a[2], a[3], b[2], b[3]);
        }
    }

    // ---- epilogue: probs + residual + LayerNorm, write into Xs ----
#pragma unroll
    for (int half = 0; half < 2; half++) {
        int row = warpM + g + half * 8;
        float* Xr = Xs + row * 65;
        float sum = 0.f, sq = 0.f;
#pragma unroll
        for (int nt = 0; nt < 8; nt++) {
            int j = nt * 8 + t4 * 2;
            float x0 = Xr[j], x1 = Xr[j + 1];
            float br0 = c[nt][half * 2 + 0];
            float bi0 = c[nt + 8][half * 2 + 0];
            float br1 = c[nt][half * 2 + 1];
            float bi1 = c[nt + 8][half * 2 + 1];
            float v0 = fmaf(br0, br0, bi0 * bi0) + x0;
            float v1 = fmaf(br1, br1, bi1 * bi1) + x1;
            c[nt][half * 2 + 0] = v0;
            c[nt][half * 2 + 1] = v1;
            sum += v0 + v1;
            sq = fmaf(v0, v0, fmaf(v1, v1, sq));
        }
        sum += __shfl_xor_sync(0xffffffffu, sum, 1);
        sum += __shfl_xor_sync(0xffffffffu, sum, 2);
        sq  += __shfl_xor_sync(0xffffffffu, sq, 1);
        sq  += __shfl_xor_sync(0xffffffffu, sq, 2);
        float mu = sum * (1.f / 64.f);
        float vv = sq * (1.f / 64.f) - mu * mu;
        float rstd = rsqrtf(vv + 1e-5f);
#pragma unroll
        for (int nt = 0; nt < 8; nt++) {
            int j = nt * 8 + t4 * 2;
            Xr[j]     = fmaf((c[nt][half * 2 + 0] - mu) * rstd, gb[j],     gb[64 + j]);
            Xr[j + 1] = fmaf((c[nt][half * 2 + 1] - mu) * rstd, gb[j + 1], gb[64 + j + 1]);
        }
    }
    __syncthreads();

    // ---- coalesced store out ----
    {
        float4* o4 = (float4*)out;
        size_t tb4 = (size_t)blockIdx.x * 2048;
        size_t lim = (size_t)nsamp * 16;
#pragma unroll
        for (int i = 0; i < 8; i++) {
            int e = tid + 256 * i;
            int row = e >> 4, cc = (e & 15) * 4;
            float* p = Xs + row * 65 + cc;
            float4 v = make_float4(p[0], p[1], p[2], p[3]);
            size_t gaddr = tb4 + e;
            if (gaddr < lim) o4[gaddr] = v;
        }
    }
}

// ---------------- launch ----------------
extern "C" void kernel_launch(void* const* d_in, const int* in_sizes, int n_in,
                              void* d_out, int out_size) {
    const float* x      = (const float*)d_in[0];
    const float* var    = (const float*)d_in[1];
    const float* gamma_ = (const float*)d_in[2];
    const float* beta_  = (const float*)d_in[3];
    float* out = (float*)d_out;

    int nsamp = in_sizes[0] / 64;

    cudaFuncSetAttribute(ffb_mma_kernel,
                         cudaFuncAttributeMaxDynamicSharedMemorySize, SMEM_DYN);

    build_W_kernel<<<64, 32>>>(var);

    int blocks = (nsamp + 127) / 128;
    ffb_mma_kernel<<<blocks, 256, SMEM_DYN>>>(x, gamma_, beta_, out, nsamp);
}